// round 9
// baseline (speedup 1.0000x reference)
#include <cuda_runtime.h>
#include <math.h>

#define N_MEM   500000
#define D_LAT   512
#define D_Q     768
#define NBINS   4096
#define CAP     1024
#define SIMS_GRID 592                       // 4 blocks/SM * 148
#define SIMS_WARPS (SIMS_GRID * 8)          // 4736
#define SIMS_STRIDE (SIMS_WARPS * 2)        // rows per grid-iteration
#define FILT_GRID 512
#define RER_GRID 32                         // j-major: block = 16 j rows

__device__ __align__(16) float g_q[D_LAT];
__device__ float g_ss_part[64];
__device__ __align__(16) float g_aj[D_LAT];
__device__ __align__(16) float g_sims[N_MEM];
__device__ unsigned g_hist[NBINS];
__device__ unsigned g_tkey;
__device__ int g_ncand;
__device__ float g_cv[CAP];
__device__ int   g_ci[CAP];
__device__ float g_rpart[RER_GRID * 32];
__device__ int g_tick1, g_tick3;

__device__ __forceinline__ float warp_sum(float v) {
#pragma unroll
    for (int o = 16; o; o >>= 1) v += __shfl_xor_sync(0xffffffffu, v, o);
    return v;
}

// monotonic float->uint key: order-preserving over all floats
__device__ __forceinline__ unsigned mkey(float f) {
    unsigned u = __float_as_uint(f);
    return (u & 0x80000000u) ? ~u : (u | 0x80000000u);
}

// ---------------------------------------------------------------------------
// 1) q = Wp @ query + bp. 64 blocks x 256 thr, warp-per-row (8 rows/block).
//    Also resets g_hist / counters for this replay (graph-replay safe).
__global__ void __launch_bounds__(256) k_proj(const float* __restrict__ query,
                                              const float* __restrict__ Wp,
                                              const float* __restrict__ bp) {
    __shared__ float4 qs[D_Q / 4];
    __shared__ float red[8];
    int t = threadIdx.x, blk = blockIdx.x;
    int gt = blk * 256 + t;
    if (gt < NBINS) g_hist[gt] = 0;
    if (gt == 0) { g_ncand = 0; g_tick1 = 0; g_tick3 = 0; }
    for (int i = t; i < D_Q / 4; i += 256) qs[i] = ((const float4*)query)[i];
    __syncthreads();
    int w = t >> 5, lane = t & 31;
    int r = blk * 8 + w;
    const float4* p = (const float4*)(Wp + (size_t)r * D_Q);
    float4 a0 = p[lane],        a1 = p[lane + 32],  a2 = p[lane + 64];
    float4 a3 = p[lane + 96],   a4 = p[lane + 128], a5 = p[lane + 160];
    float4 q0 = qs[lane],       q1 = qs[lane + 32], q2 = qs[lane + 64];
    float4 q3 = qs[lane + 96],  q4 = qs[lane + 128], q5 = qs[lane + 160];
    float d = a0.x * q0.x + a0.y * q0.y + a0.z * q0.z + a0.w * q0.w
            + a1.x * q1.x + a1.y * q1.y + a1.z * q1.z + a1.w * q1.w
            + a2.x * q2.x + a2.y * q2.y + a2.z * q2.z + a2.w * q2.w
            + a3.x * q3.x + a3.y * q3.y + a3.z * q3.z + a3.w * q3.w
            + a4.x * q4.x + a4.y * q4.y + a4.z * q4.z + a4.w * q4.w
            + a5.x * q5.x + a5.y * q5.y + a5.z * q5.z + a5.w * q5.w;
    d = warp_sum(d);
    if (lane == 0) {
        float v = d + bp[r];
        g_q[r] = v;
        red[w] = v * v;
    }
    __syncthreads();
    if (t == 0) {
        float s = 0.f;
        for (int i = 0; i < 8; i++) s += red[i];
        g_ss_part[blk] = s;
    }
}

// ---------------------------------------------------------------------------
// 2) sims[i] = dot(mem_i, qn)/(||mem_i||+1e-8). Persistent, 2 rows/warp/iter.
//    Blocks 0..31 additionally compute a_j (hidden under the memory pass).
//    Fused smem histogram; LAST block computes the threshold key.
__global__ void __launch_bounds__(256, 4) k_sims(const float* __restrict__ mem,
                                                 const float* __restrict__ W1,
                                                 const float* __restrict__ b1) {
    __shared__ float4 qsh[D_LAT / 4];
    __shared__ unsigned hist[NBINS];
    __shared__ unsigned part[256];
    __shared__ int is_last;
    int t = threadIdx.x;
    int w = t >> 5, lane = t & 31;

    // --- aj sub-task on blocks 0..31: a_j = b1[j] + dot(q, W1[j,0:512]) ---
    if (blockIdx.x < 32) {
        int j0 = blockIdx.x * 16 + w * 2, j1 = j0 + 1;
        const float4* p0 = (const float4*)(W1 + (size_t)j0 * (2 * D_LAT));
        const float4* p1 = (const float4*)(W1 + (size_t)j1 * (2 * D_LAT));
        float d0 = 0.f, d1 = 0.f;
#pragma unroll
        for (int u = 0; u < 4; u++) {
            float4 a = p0[lane + 32 * u];
            float4 b = p1[lane + 32 * u];
            float4 q = ((const float4*)g_q)[lane + 32 * u];
            d0 += a.x * q.x + a.y * q.y + a.z * q.z + a.w * q.w;
            d1 += b.x * q.x + b.y * q.y + b.z * q.z + b.w * q.w;
        }
        d0 = warp_sum(d0); d1 = warp_sum(d1);
        if (lane == 0) { g_aj[j0] = d0 + b1[j0]; g_aj[j1] = d1 + b1[j1]; }
    }

    float ss = 0.f;
#pragma unroll
    for (int i = 0; i < 64; i++) ss += g_ss_part[i];
    float inv = 1.0f / (sqrtf(ss) + 1e-8f);
    for (int i = t; i < D_LAT / 4; i += 256) {
        float4 q = ((const float4*)g_q)[i];
        q.x *= inv; q.y *= inv; q.z *= inv; q.w *= inv;
        qsh[i] = q;
    }
    for (int i = t; i < NBINS; i += 256) hist[i] = 0;
    __syncthreads();
    int wg = blockIdx.x * 8 + w;
    for (int base = wg * 2; base < N_MEM; base += SIMS_STRIDE) {
        const float4* r0 = (const float4*)(mem + (size_t)base * D_LAT);
        const float4* r1 = (const float4*)(mem + (size_t)(base + 1) * D_LAT);
        float d0 = 0.f, s0 = 0.f, d1 = 0.f, s1 = 0.f;
#pragma unroll
        for (int u = 0; u < 4; u++) {
            float4 a = r0[lane + 32 * u];
            float4 b = r1[lane + 32 * u];
            float4 q = qsh[lane + 32 * u];
            d0 += a.x * q.x + a.y * q.y + a.z * q.z + a.w * q.w;
            s0 += a.x * a.x + a.y * a.y + a.z * a.z + a.w * a.w;
            d1 += b.x * q.x + b.y * q.y + b.z * q.z + b.w * q.w;
            s1 += b.x * b.x + b.y * b.y + b.z * b.z + b.w * b.w;
        }
        d0 = warp_sum(d0); s0 = warp_sum(s0);
        d1 = warp_sum(d1); s1 = warp_sum(s1);
        if (lane == 0) {
            float v0 = d0 / (sqrtf(s0) + 1e-8f);
            float v1 = d1 / (sqrtf(s1) + 1e-8f);
            g_sims[base] = v0;
            g_sims[base + 1] = v1;
            atomicAdd(&hist[mkey(v0) >> 20], 1u);
            atomicAdd(&hist[mkey(v1) >> 20], 1u);
        }
    }
    __syncthreads();
    for (int i = t; i < NBINS; i += 256) {
        unsigned c = hist[i];
        if (c) atomicAdd(&g_hist[i], c);
    }
    __syncthreads();
    if (t == 0) {
        __threadfence();
        is_last = (atomicAdd(&g_tick1, 1) == SIMS_GRID - 1);
    }
    __syncthreads();
    if (!is_last) return;

    // --- threshold epilogue (only last block) ---
    unsigned s16 = 0;
#pragma unroll
    for (int i = 0; i < 16; i++) s16 += g_hist[t * 16 + i];
    part[t] = s16;
    __syncthreads();
    if (w == 0) {
        unsigned c8 = 0;
#pragma unroll
        for (int i = 0; i < 8; i++) c8 += part[lane * 8 + i];
        unsigned suf = c8;
#pragma unroll
        for (int o = 1; o < 32; o <<= 1) {
            unsigned x = __shfl_down_sync(0xffffffffu, suf, o);
            if (lane + o < 32) suf += x;
        }
        unsigned above = __shfl_down_sync(0xffffffffu, suf, 1);
        if (lane == 31) above = 0;
        unsigned mask = __ballot_sync(0xffffffffu, suf >= 32u);
        int Lstar = 31 - __clz(mask);   // highest lane whose suffix >= 32
        if (lane == Lstar) {
            unsigned cum = above;
            int seg = Lstar * 8 + 7;
            for (; seg > Lstar * 8; seg--) {
                if (cum + part[seg] >= 32u) break;
                cum += part[seg];
            }
            int bin = seg * 16 + 15;
            for (; bin > seg * 16; bin--) {
                cum += g_hist[bin];
                if (cum >= 32u) break;
            }
            g_tkey = ((unsigned)bin) << 20;
        }
    }
}

// ---------------------------------------------------------------------------
// 3) filter: pure compaction of sims with key >= threshold (no epilogue).
__global__ void __launch_bounds__(256) k_filter() {
    int t = threadIdx.x, blk = blockIdx.x;
    unsigned tkey = g_tkey;
    for (int i4 = blk * 256 + t; i4 < N_MEM / 4; i4 += FILT_GRID * 256) {
        float4 v = ((const float4*)g_sims)[i4];
        int i = i4 * 4;
        if (mkey(v.x) >= tkey) { int p = atomicAdd(&g_ncand, 1); if (p < CAP) { g_cv[p] = v.x; g_ci[p] = i; } }
        if (mkey(v.y) >= tkey) { int p = atomicAdd(&g_ncand, 1); if (p < CAP) { g_cv[p] = v.y; g_ci[p] = i + 1; } }
        if (mkey(v.z) >= tkey) { int p = atomicAdd(&g_ncand, 1); if (p < CAP) { g_cv[p] = v.z; g_ci[p] = i + 2; } }
        if (mkey(v.w) >= tkey) { int p = atomicAdd(&g_ncand, 1); if (p < CAP) { g_cv[p] = v.w; g_ci[p] = i + 3; } }
    }
}

// ---------------------------------------------------------------------------
// 4) rerank, j-major (32 blocks x 512 thr; block b owns j in [b*16, b*16+16)).
//    Each block REDUNDANTLY derives the top-32 candidates from the compacted
//    survivors via a single-warp bitonic sort by (mkey desc, idx asc) — a
//    strict total order, so every block gets the identical deterministic
//    result (compaction order irrelevant). W1 row / a_j / W2 prefetched into
//    registers before anything else. Compute loop uses 4-way interleaved
//    warp reductions. Fixed j-ascending combine; LAST block writes top-16.
__global__ void __launch_bounds__(512) k_rerank(const float* __restrict__ mem,
                                                const float* __restrict__ W1,
                                                const float* __restrict__ W2,
                                                const float* __restrict__ b2,
                                                float* __restrict__ out,
                                                int out_size) {
    __shared__ float4 cs[32 * (D_LAT / 4)];   // 64 KB: all candidate rows
    __shared__ float jacc[16][32];            // [warp(j)][candidate]
    __shared__ unsigned skv[64];
    __shared__ int      ski[64];
    __shared__ float pr[RER_GRID * 32];
    __shared__ float fsc[32];
    __shared__ int   fid[32];
    __shared__ int is_last;
    int t = threadIdx.x, blk = blockIdx.x;
    int w = t >> 5, lane = t & 31;
    int j = blk * 16 + w;

    // prefetch: W1 row, a_j, W2[j] (independent of candidate selection)
    const float4* wrow = (const float4*)(W1 + (size_t)j * (2 * D_LAT) + D_LAT);
    float4 w0 = wrow[lane], w1r = wrow[lane + 32], w2r = wrow[lane + 64], w3r = wrow[lane + 96];
    float ajv = g_aj[j];
    float w2j = W2[j];

    // load survivors into smem (padded to 64 with rank-last sentinels)
    int n = g_ncand; if (n > CAP) n = CAP;
    if (t < 64) {
        if (t < n) { skv[t] = mkey(g_cv[t]); ski[t] = g_ci[t]; }
        else       { skv[t] = 0u;            ski[t] = 0x7fffffff; }
    }
    __syncthreads();

    if (n <= 64) {
        // single-warp bitonic sort, best-first by (key desc, idx asc)
        if (w == 0) {
            for (int size = 2; size <= 64; size <<= 1) {
                for (int stride = size >> 1; stride > 0; stride >>= 1) {
#pragma unroll
                    for (int rep = 0; rep < 2; rep++) {
                        int i = lane + rep * 32;
                        int p = i ^ stride;
                        if (p > i) {
                            unsigned ka = skv[i], kb = skv[p];
                            int ia = ski[i], ib = ski[p];
                            bool a_first = (ka > kb) || (ka == kb && ia < ib);
                            bool up = ((i & size) == 0);
                            if (up != a_first) {
                                skv[i] = kb; skv[p] = ka;
                                ski[i] = ib; ski[p] = ia;
                            }
                        }
                    }
                    __syncwarp();
                }
            }
        }
    } else {
        // rare fallback: serial stable select (same total order), no mutation
        if (w == 0) {
            unsigned pk = 0xffffffffu; int pi = -1;   // previous pick (rank sentinel: before everything)
            for (int r = 0; r < 32; r++) {
                unsigned bk = 0u; int bi = 0x7fffffff;
                for (int i = lane; i < n; i += 32) {
                    unsigned ke = mkey(g_cv[i]); int ie = g_ci[i];
                    // must rank strictly after previous pick
                    bool after = (ke < pk) || (ke == pk && ie > pi);
                    if (after && ((ke > bk) || (ke == bk && ie < bi))) { bk = ke; bi = ie; }
                }
#pragma unroll
                for (int o = 16; o; o >>= 1) {
                    unsigned ok = __shfl_xor_sync(0xffffffffu, bk, o);
                    int oi = __shfl_xor_sync(0xffffffffu, bi, o);
                    if ((ok > bk) || (ok == bk && oi < bi)) { bk = ok; bi = oi; }
                }
                if (lane == 0) { skv[r] = bk; ski[r] = bi; }
                pk = bk; pi = bi;
                __syncwarp();
            }
        }
    }
    __syncthreads();

    // gather all 32 candidate rows into smem (indices from smem, no indirection)
    for (int i = t; i < 32 * (D_LAT / 4); i += 512) {
        int c = i >> 7;            // / 128
        int off = i & 127;
        cs[i] = ((const float4*)(mem + (size_t)ski[c] * D_LAT))[off];
    }
    __syncthreads();

    // each warp: its j row against 32 candidates, 4 at a time (pipelined reduces)
    for (int c0 = 0; c0 < 32; c0 += 4) {
        float d[4];
#pragma unroll
        for (int k = 0; k < 4; k++) {
            const float4* cr = &cs[(c0 + k) * (D_LAT / 4)];
            float4 x0 = cr[lane], x1 = cr[lane + 32], x2 = cr[lane + 64], x3 = cr[lane + 96];
            d[k] = w0.x * x0.x + w0.y * x0.y + w0.z * x0.z + w0.w * x0.w
                 + w1r.x * x1.x + w1r.y * x1.y + w1r.z * x1.z + w1r.w * x1.w
                 + w2r.x * x2.x + w2r.y * x2.y + w2r.z * x2.z + w2r.w * x2.w
                 + w3r.x * x3.x + w3r.y * x3.y + w3r.z * x3.z + w3r.w * x3.w;
        }
        // 4 independent shuffle-reduce chains (latency pipelined)
#pragma unroll
        for (int o = 16; o; o >>= 1) {
#pragma unroll
            for (int k = 0; k < 4; k++)
                d[k] += __shfl_xor_sync(0xffffffffu, d[k], o);
        }
        if (lane == 0) {
#pragma unroll
            for (int k = 0; k < 4; k++) {
                float h = ajv + d[k];
                jacc[w][c0 + k] = (h > 0.f) ? h * w2j : 0.f;
            }
        }
    }
    __syncthreads();

    // block combine: candidate per lane, fixed w-ascending (= j-ascending) order
    if (w == 0) {
        float s = 0.f;
#pragma unroll
        for (int k = 0; k < 16; k++) s += jacc[k][lane];
        g_rpart[blk * 32 + lane] = s;
    }
    __syncthreads();
    if (t == 0) {
        __threadfence();
        is_last = (atomicAdd(&g_tick3, 1) == RER_GRID - 1);
    }
    __syncthreads();
    if (!is_last) return;

    // --- final epilogue: fixed-order reduce over blocks + stable top-16 ---
    for (int i = t; i < RER_GRID * 32; i += 512) pr[i] = g_rpart[i];
    __syncthreads();
    if (w == 0) {
        float s = 0.f;
#pragma unroll
        for (int b = 0; b < RER_GRID; b++) s += pr[b * 32 + lane];
        fsc[lane] = s + b2[0];
        fid[lane] = ski[lane];
        __syncwarp();
        if (lane == 0) {
            for (int r = 0; r < 16; r++) {
                float bv = -1e30f; int bp = 0;
                for (int k = 0; k < 32; k++)
                    if (fsc[k] > bv) { bv = fsc[k]; bp = k; }
                if (r < out_size)      out[r]      = bv;
                if (16 + r < out_size) out[16 + r] = (float)fid[bp];
                fsc[bp] = -1e30f;
            }
        }
    }
}

// ---------------------------------------------------------------------------
extern "C" void kernel_launch(void* const* d_in, const int* in_sizes, int n_in,
                              void* d_out, int out_size) {
    const float* query  = (const float*)d_in[0];
    const float* memory = (const float*)d_in[1];
    const float* Wp     = (const float*)d_in[2];
    const float* bp     = (const float*)d_in[3];
    const float* W1     = (const float*)d_in[4];
    const float* b1     = (const float*)d_in[5];
    const float* W2     = (const float*)d_in[6];
    const float* b2     = (const float*)d_in[7];
    (void)in_sizes; (void)n_in;

    k_proj  <<<64, 256>>>(query, Wp, bp);
    k_sims  <<<SIMS_GRID, 256>>>(memory, W1, b1);
    k_filter<<<FILT_GRID, 256>>>();
    k_rerank<<<RER_GRID, 512>>>(memory, W1, W2, b2, (float*)d_out, out_size);
}

// round 12
// speedup vs baseline: 1.0530x; 1.0530x over previous
#include <cuda_runtime.h>
#include <math.h>

#define N_MEM   500000
#define D_LAT   512
#define D_Q     768
#define NBINS   4096
#define CAP     1024
#define SIMS_GRID 592                       // 4 blocks/SM * 148
#define SIMS_WARPS (SIMS_GRID * 8)          // 4736
#define SIMS_STRIDE (SIMS_WARPS * 2)        // rows per grid-iteration
#define FILT_GRID 512
#define RER_GRID 256                        // 32 candidates x 8 j-chunks

__device__ __align__(16) float g_q[D_LAT];
__device__ float g_ss_part[64];
__device__ __align__(16) float g_aj[D_LAT];
__device__ __align__(16) float g_sims[N_MEM];
__device__ unsigned g_hist[NBINS];
__device__ unsigned g_tkey;
__device__ int g_ncand;
__device__ float g_cv[CAP];
__device__ int   g_ci[CAP];
__device__ int   g_cand[32];
__device__ float g_rpart[RER_GRID];
__device__ int g_tick1, g_tick2, g_tick3;

__device__ __forceinline__ float warp_sum(float v) {
#pragma unroll
    for (int o = 16; o; o >>= 1) v += __shfl_xor_sync(0xffffffffu, v, o);
    return v;
}

// monotonic float->uint key: order-preserving over all floats
__device__ __forceinline__ unsigned mkey(float f) {
    unsigned u = __float_as_uint(f);
    return (u & 0x80000000u) ? ~u : (u | 0x80000000u);
}

// ---------------------------------------------------------------------------
// 1) q = Wp @ query + bp. 64 blocks x 256 thr, warp-per-row (8 rows/block).
//    Also resets g_hist / counters for this replay (graph-replay safe).
__global__ void __launch_bounds__(256) k_proj(const float* __restrict__ query,
                                              const float* __restrict__ Wp,
                                              const float* __restrict__ bp) {
    __shared__ float4 qs[D_Q / 4];
    __shared__ float red[8];
    int t = threadIdx.x, blk = blockIdx.x;
    int gt = blk * 256 + t;
    if (gt < NBINS) g_hist[gt] = 0;
    if (gt == 0) { g_ncand = 0; g_tick1 = 0; g_tick2 = 0; g_tick3 = 0; }
    for (int i = t; i < D_Q / 4; i += 256) qs[i] = ((const float4*)query)[i];
    __syncthreads();
    int w = t >> 5, lane = t & 31;
    int r = blk * 8 + w;
    const float4* p = (const float4*)(Wp + (size_t)r * D_Q);
    float4 a0 = p[lane],        a1 = p[lane + 32],  a2 = p[lane + 64];
    float4 a3 = p[lane + 96],   a4 = p[lane + 128], a5 = p[lane + 160];
    float4 q0 = qs[lane],       q1 = qs[lane + 32], q2 = qs[lane + 64];
    float4 q3 = qs[lane + 96],  q4 = qs[lane + 128], q5 = qs[lane + 160];
    float d = a0.x * q0.x + a0.y * q0.y + a0.z * q0.z + a0.w * q0.w
            + a1.x * q1.x + a1.y * q1.y + a1.z * q1.z + a1.w * q1.w
            + a2.x * q2.x + a2.y * q2.y + a2.z * q2.z + a2.w * q2.w
            + a3.x * q3.x + a3.y * q3.y + a3.z * q3.z + a3.w * q3.w
            + a4.x * q4.x + a4.y * q4.y + a4.z * q4.z + a4.w * q4.w
            + a5.x * q5.x + a5.y * q5.y + a5.z * q5.z + a5.w * q5.w;
    d = warp_sum(d);
    if (lane == 0) {
        float v = d + bp[r];
        g_q[r] = v;
        red[w] = v * v;
    }
    __syncthreads();
    if (t == 0) {
        float s = 0.f;
        for (int i = 0; i < 8; i++) s += red[i];
        g_ss_part[blk] = s;
    }
}

// ---------------------------------------------------------------------------
// 2) sims[i] = dot(mem_i, qn)/(||mem_i||+1e-8). Persistent, 2 rows/warp/iter.
//    Blocks 0..31 additionally compute a_j (hidden under the memory pass).
//    Fused smem histogram; LAST block computes the threshold key.
__global__ void __launch_bounds__(256, 4) k_sims(const float* __restrict__ mem,
                                                 const float* __restrict__ W1,
                                                 const float* __restrict__ b1) {
    __shared__ float4 qsh[D_LAT / 4];
    __shared__ unsigned hist[NBINS];
    __shared__ unsigned part[256];
    __shared__ int is_last;
    int t = threadIdx.x;
    int w = t >> 5, lane = t & 31;

    // --- aj sub-task on blocks 0..31: a_j = b1[j] + dot(q, W1[j,0:512]) ---
    if (blockIdx.x < 32) {
        int j0 = blockIdx.x * 16 + w * 2, j1 = j0 + 1;
        const float4* p0 = (const float4*)(W1 + (size_t)j0 * (2 * D_LAT));
        const float4* p1 = (const float4*)(W1 + (size_t)j1 * (2 * D_LAT));
        float d0 = 0.f, d1 = 0.f;
#pragma unroll
        for (int u = 0; u < 4; u++) {
            float4 a = p0[lane + 32 * u];
            float4 b = p1[lane + 32 * u];
            float4 q = ((const float4*)g_q)[lane + 32 * u];
            d0 += a.x * q.x + a.y * q.y + a.z * q.z + a.w * q.w;
            d1 += b.x * q.x + b.y * q.y + b.z * q.z + b.w * q.w;
        }
        d0 = warp_sum(d0); d1 = warp_sum(d1);
        if (lane == 0) { g_aj[j0] = d0 + b1[j0]; g_aj[j1] = d1 + b1[j1]; }
    }

    float ss = 0.f;
#pragma unroll
    for (int i = 0; i < 64; i++) ss += g_ss_part[i];
    float inv = 1.0f / (sqrtf(ss) + 1e-8f);
    for (int i = t; i < D_LAT / 4; i += 256) {
        float4 q = ((const float4*)g_q)[i];
        q.x *= inv; q.y *= inv; q.z *= inv; q.w *= inv;
        qsh[i] = q;
    }
    for (int i = t; i < NBINS; i += 256) hist[i] = 0;
    __syncthreads();
    int wg = blockIdx.x * 8 + w;
    for (int base = wg * 2; base < N_MEM; base += SIMS_STRIDE) {
        const float4* r0 = (const float4*)(mem + (size_t)base * D_LAT);
        const float4* r1 = (const float4*)(mem + (size_t)(base + 1) * D_LAT);
        float d0 = 0.f, s0 = 0.f, d1 = 0.f, s1 = 0.f;
#pragma unroll
        for (int u = 0; u < 4; u++) {
            float4 a = r0[lane + 32 * u];
            float4 b = r1[lane + 32 * u];
            float4 q = qsh[lane + 32 * u];
            d0 += a.x * q.x + a.y * q.y + a.z * q.z + a.w * q.w;
            s0 += a.x * a.x + a.y * a.y + a.z * a.z + a.w * a.w;
            d1 += b.x * q.x + b.y * q.y + b.z * q.z + b.w * q.w;
            s1 += b.x * b.x + b.y * b.y + b.z * b.z + b.w * b.w;
        }
        d0 = warp_sum(d0); s0 = warp_sum(s0);
        d1 = warp_sum(d1); s1 = warp_sum(s1);
        if (lane == 0) {
            float v0 = d0 / (sqrtf(s0) + 1e-8f);
            float v1 = d1 / (sqrtf(s1) + 1e-8f);
            g_sims[base] = v0;
            g_sims[base + 1] = v1;
            atomicAdd(&hist[mkey(v0) >> 20], 1u);
            atomicAdd(&hist[mkey(v1) >> 20], 1u);
        }
    }
    __syncthreads();
    for (int i = t; i < NBINS; i += 256) {
        unsigned c = hist[i];
        if (c) atomicAdd(&g_hist[i], c);
    }
    __syncthreads();
    if (t == 0) {
        __threadfence();
        is_last = (atomicAdd(&g_tick1, 1) == SIMS_GRID - 1);
    }
    __syncthreads();
    if (!is_last) return;

    // --- threshold epilogue (only last block) ---
    unsigned s16 = 0;
#pragma unroll
    for (int i = 0; i < 16; i++) s16 += g_hist[t * 16 + i];
    part[t] = s16;
    __syncthreads();
    if (w == 0) {
        unsigned c8 = 0;
#pragma unroll
        for (int i = 0; i < 8; i++) c8 += part[lane * 8 + i];
        unsigned suf = c8;
#pragma unroll
        for (int o = 1; o < 32; o <<= 1) {
            unsigned x = __shfl_down_sync(0xffffffffu, suf, o);
            if (lane + o < 32) suf += x;
        }
        unsigned above = __shfl_down_sync(0xffffffffu, suf, 1);
        if (lane == 31) above = 0;
        unsigned mask = __ballot_sync(0xffffffffu, suf >= 32u);
        int Lstar = 31 - __clz(mask);   // highest lane whose suffix >= 32
        if (lane == Lstar) {
            unsigned cum = above;
            int seg = Lstar * 8 + 7;
            for (; seg > Lstar * 8; seg--) {
                if (cum + part[seg] >= 32u) break;
                cum += part[seg];
            }
            int bin = seg * 16 + 15;
            for (; bin > seg * 16; bin--) {
                cum += g_hist[bin];
                if (cum >= 32u) break;
            }
            g_tkey = ((unsigned)bin) << 20;
        }
    }
}

// ---------------------------------------------------------------------------
// 3) filter: compact sims with key >= threshold; LAST block runs the exact
//    stable top-32 select over an smem copy with a single warp.
__global__ void __launch_bounds__(256) k_filter() {
    __shared__ float sv[CAP];
    __shared__ int   si[CAP];
    __shared__ int is_last;
    int t = threadIdx.x, blk = blockIdx.x;
    int w = t >> 5, lane = t & 31;

    unsigned tkey = g_tkey;
    for (int i4 = blk * 256 + t; i4 < N_MEM / 4; i4 += FILT_GRID * 256) {
        float4 v = ((const float4*)g_sims)[i4];
        int i = i4 * 4;
        if (mkey(v.x) >= tkey) { int p = atomicAdd(&g_ncand, 1); if (p < CAP) { g_cv[p] = v.x; g_ci[p] = i; } }
        if (mkey(v.y) >= tkey) { int p = atomicAdd(&g_ncand, 1); if (p < CAP) { g_cv[p] = v.y; g_ci[p] = i + 1; } }
        if (mkey(v.z) >= tkey) { int p = atomicAdd(&g_ncand, 1); if (p < CAP) { g_cv[p] = v.z; g_ci[p] = i + 2; } }
        if (mkey(v.w) >= tkey) { int p = atomicAdd(&g_ncand, 1); if (p < CAP) { g_cv[p] = v.w; g_ci[p] = i + 3; } }
    }
    if (t == 0) {
        __threadfence();
        is_last = (atomicAdd(&g_tick2, 1) == FILT_GRID - 1);
    }
    __syncthreads();
    if (!is_last) return;

    // --- select epilogue: copy survivors to smem once, one warp selects ---
    int n = g_ncand; if (n > CAP) n = CAP;
    for (int i = t; i < n; i += 256) { sv[i] = g_cv[i]; si[i] = g_ci[i]; }
    __syncthreads();
    if (w == 0) {
        for (int r = 0; r < 32; r++) {
            float bv = -1e30f; int bi = 0x7fffffff, bp = -1;
            for (int i = lane; i < n; i += 32) {
                float v = sv[i]; int idx = si[i];
                if (v > bv || (v == bv && idx < bi)) { bv = v; bi = idx; bp = i; }
            }
#pragma unroll
            for (int o = 16; o; o >>= 1) {
                float ov = __shfl_xor_sync(0xffffffffu, bv, o);
                int oi = __shfl_xor_sync(0xffffffffu, bi, o);
                int op = __shfl_xor_sync(0xffffffffu, bp, o);
                if (ov > bv || (ov == bv && oi < bi)) { bv = ov; bi = oi; bp = op; }
            }
            if (lane == 0) {
                g_cand[r] = bi;
                if (bp >= 0) sv[bp] = -1e30f;
            }
            __syncwarp();
        }
    }
}

// ---------------------------------------------------------------------------
// 4) rerank (R5 structure): block = c*8 + chunk (32 candidates x 8 chunks of
//    64 j). 16 warps x 4 j (2-way ILP x 2 iters). LAST block reduces the 8
//    partials per candidate in fixed order via one PARALLEL smem load of all
//    256 partials, adds b2, and writes the final stable top-16.
__global__ void __launch_bounds__(512) k_rerank(const float* __restrict__ mem,
                                                const float* __restrict__ W1,
                                                const float* __restrict__ W2,
                                                const float* __restrict__ b2,
                                                float* __restrict__ out,
                                                int out_size) {
    __shared__ float4 cs[D_LAT / 4];
    __shared__ float wacc[16];
    __shared__ int is_last;
    int blk = blockIdx.x, t = threadIdx.x;
    int c = blk >> 3, chunk = blk & 7;
    int cidx = g_cand[c];
    for (int i = t; i < D_LAT / 4; i += 512)
        cs[i] = ((const float4*)(mem + (size_t)cidx * D_LAT))[i];
    __syncthreads();
    int w = t >> 5, lane = t & 31;
    float acc = 0.f;
#pragma unroll
    for (int jj = 0; jj < 4; jj += 2) {
        int j0 = chunk * 64 + w * 4 + jj, j1 = j0 + 1;
        const float4* p0 = (const float4*)(W1 + (size_t)j0 * (2 * D_LAT) + D_LAT);
        const float4* p1 = (const float4*)(W1 + (size_t)j1 * (2 * D_LAT) + D_LAT);
        float d0 = 0.f, d1 = 0.f;
#pragma unroll
        for (int u = 0; u < 4; u++) {
            float4 a = p0[lane + 32 * u];
            float4 b = p1[lane + 32 * u];
            float4 q = cs[lane + 32 * u];
            d0 += a.x * q.x + a.y * q.y + a.z * q.z + a.w * q.w;
            d1 += b.x * q.x + b.y * q.y + b.z * q.z + b.w * q.w;
        }
        d0 = warp_sum(d0); d1 = warp_sum(d1);
        if (lane == 0) {
            float h0 = g_aj[j0] + d0; if (h0 > 0.f) acc += h0 * W2[j0];
            float h1 = g_aj[j1] + d1; if (h1 > 0.f) acc += h1 * W2[j1];
        }
    }
    if (lane == 0) wacc[w] = acc;
    __syncthreads();
    if (t == 0) {
        float s = 0.f;
#pragma unroll
        for (int i = 0; i < 16; i++) s += wacc[i];
        g_rpart[blk] = s;
        __threadfence();
        is_last = (atomicAdd(&g_tick3, 1) == RER_GRID - 1);
    }
    __syncthreads();
    if (!is_last) return;

    // --- final epilogue: parallel partial load + fixed-order reduce + top-16
    __shared__ float pr[RER_GRID];
    __shared__ float fsc[32];
    __shared__ int   fid[32];
    if (t < RER_GRID) pr[t] = g_rpart[t];
    __syncthreads();
    if (w == 0) {
        float s = 0.f;
#pragma unroll
        for (int p = 0; p < 8; p++) s += pr[lane * 8 + p];
        fsc[lane] = s + b2[0];
        fid[lane] = g_cand[lane];
        __syncwarp();
        if (lane == 0) {
            for (int r = 0; r < 16; r++) {
                float bv = -1e30f; int bp = 0;
                for (int k = 0; k < 32; k++)
                    if (fsc[k] > bv) { bv = fsc[k]; bp = k; }
                if (r < out_size)      out[r]      = bv;
                if (16 + r < out_size) out[16 + r] = (float)fid[bp];
                fsc[bp] = -1e30f;
            }
        }
    }
}

// ---------------------------------------------------------------------------
extern "C" void kernel_launch(void* const* d_in, const int* in_sizes, int n_in,
                              void* d_out, int out_size) {
    const float* query  = (const float*)d_in[0];
    const float* memory = (const float*)d_in[1];
    const float* Wp     = (const float*)d_in[2];
    const float* bp     = (const float*)d_in[3];
    const float* W1     = (const float*)d_in[4];
    const float* b1     = (const float*)d_in[5];
    const float* W2     = (const float*)d_in[6];
    const float* b2     = (const float*)d_in[7];
    (void)in_sizes; (void)n_in;

    k_proj  <<<64, 256>>>(query, Wp, bp);
    k_sims  <<<SIMS_GRID, 256>>>(memory, W1, b1);
    k_filter<<<FILT_GRID, 256>>>();
    k_rerank<<<RER_GRID, 512>>>(memory, W1, W2, b2, (float*)d_out, out_size);
}